// round 9
// baseline (speedup 1.0000x reference)
#include <cuda_runtime.h>
#include <math.h>

typedef unsigned long long ull;
#define NCTA 128
#define TPB  512

// ---- device scratch (static; allocations forbidden) ----
__device__ float g_u[512u*1024u*64u];   // u[t][d][b]
__device__ float g_s[512u*1024u*64u];   // states[t][d][b]
__device__ float g_x[2][1024*64];       // state ping-pong, layout [k][b]
__device__ int   g_len[64];
__device__ unsigned g_bar_count;
__device__ unsigned g_bar_gen;

// ---- packed f32x2 helpers ----
__device__ __forceinline__ ull pack2(float a, float b){ ull r; asm("mov.b64 %0,{%1,%2};":"=l"(r):"f"(a),"f"(b)); return r; }
__device__ __forceinline__ float2 unpk(ull v){ float2 r; asm("mov.b64 {%0,%1},%2;":"=f"(r.x),"=f"(r.y):"l"(v)); return r; }
__device__ __forceinline__ ull ffma2(ull a, ull b, ull c){ ull d; asm("fma.rn.f32x2 %0,%1,%2,%3;":"=l"(d):"l"(a),"l"(b),"l"(c)); return d; }
__device__ __forceinline__ ull add2(ull a, ull b){ ull d; asm("add.rn.f32x2 %0,%1,%2;":"=l"(d):"l"(a),"l"(b)); return d; }

// ---- init ----
__global__ void init_kernel(const float* __restrict__ x0) {
    int idx = blockIdx.x * 256 + threadIdx.x;
    g_x[0][idx] = x0[idx >> 6];
    if (idx < 64) g_len[idx] = 0;
}

// ---- lengths ----
__global__ void len_kernel(const float* __restrict__ emb) {
    int t = blockIdx.x;
    int b = threadIdx.x >> 2, p = threadIdx.x & 3;
    const float* row = emb + ((size_t)t*64 + b)*300;
    float s = 0.f;
    for (int i = p; i < 300; i += 4) s += row[i];
    s += __shfl_xor_sync(0xffffffffu, s, 1);
    s += __shfl_xor_sync(0xffffffffu, s, 2);
    if (p == 0 && s != 0.f) atomicAdd(&g_len[b], 1);
}

// ---- projection: 2 timesteps/block, float4-coalesced global loads ----
__global__ __launch_bounds__(256) void proj_kernel(const float* __restrict__ emb,
                                                   const float* __restrict__ win,
                                                   const float* __restrict__ bias) {
    __align__(16) __shared__ float Es[2][32][66];
    __align__(16) __shared__ ull   Wd[32][66];
    const int tid = threadIdx.x;
    const int tx = tid & 15;
    const int ty = tid >> 4;
    const int t0 = blockIdx.y * 2;
    const int d0 = blockIdx.x * 64;

    ull acc[2][4][2];
    #pragma unroll
    for (int h = 0; h < 2; ++h)
        #pragma unroll
        for (int i = 0; i < 4; ++i) { acc[h][i][0] = 0ull; acc[h][i][1] = 0ull; }

    for (int k0 = 0; k0 < 300; k0 += 32) {
        #pragma unroll
        for (int p = 0; p < 4; ++p) {
            int idx = tid + 256*p;
            int h = idx >> 9, rem = idx & 511;
            int b = rem >> 3, kq = rem & 7;
            int k = k0 + 4*kq;
            float4 v = make_float4(0.f, 0.f, 0.f, 0.f);
            if (k + 3 < 300) v = *(const float4*)&emb[((size_t)(t0+h)*64 + b)*300 + k];
            Es[h][4*kq+0][b] = v.x;
            Es[h][4*kq+1][b] = v.y;
            Es[h][4*kq+2][b] = v.z;
            Es[h][4*kq+3][b] = v.w;
        }
        #pragma unroll
        for (int p = 0; p < 2; ++p) {
            int idx = tid + 256*p;
            int dl = idx >> 3, kq = idx & 7;
            int k = k0 + 4*kq;
            float4 v = make_float4(0.f, 0.f, 0.f, 0.f);
            if (k + 3 < 300) v = *(const float4*)&win[((size_t)(d0+dl))*300 + k];
            Wd[4*kq+0][dl] = pack2(v.x, v.x);
            Wd[4*kq+1][dl] = pack2(v.y, v.y);
            Wd[4*kq+2][dl] = pack2(v.z, v.z);
            Wd[4*kq+3][dl] = pack2(v.w, v.w);
        }
        __syncthreads();
        #pragma unroll
        for (int kk = 0; kk < 32; ++kk) {
            ulonglong2 wA = *(const ulonglong2*)&Wd[kk][ty*4];
            ulonglong2 wB = *(const ulonglong2*)&Wd[kk][ty*4 + 2];
            #pragma unroll
            for (int h = 0; h < 2; ++h) {
                ull e01 = *(const ull*)&Es[h][kk][tx*4];
                ull e23 = *(const ull*)&Es[h][kk][tx*4 + 2];
                acc[h][0][0] = ffma2(e01, wA.x, acc[h][0][0]); acc[h][0][1] = ffma2(e23, wA.x, acc[h][0][1]);
                acc[h][1][0] = ffma2(e01, wA.y, acc[h][1][0]); acc[h][1][1] = ffma2(e23, wA.y, acc[h][1][1]);
                acc[h][2][0] = ffma2(e01, wB.x, acc[h][2][0]); acc[h][2][1] = ffma2(e23, wB.x, acc[h][2][1]);
                acc[h][3][0] = ffma2(e01, wB.y, acc[h][3][0]); acc[h][3][1] = ffma2(e23, wB.y, acc[h][3][1]);
            }
        }
        __syncthreads();
    }
    #pragma unroll
    for (int h = 0; h < 2; ++h)
        #pragma unroll
        for (int dd = 0; dd < 4; ++dd) {
            int d = d0 + ty*4 + dd;
            float bb = bias[d];
            float2 p0 = unpk(acc[h][dd][0]), p1 = unpk(acc[h][dd][1]);
            float4 o = make_float4(p0.x + bb, p0.y + bb, p1.x + bb, p1.y + bb);
            *(float4*)&g_u[((size_t)(t0+h)*1024 + d)*64 + tx*4] = o;
        }
}

// ---- grid barrier ----
__device__ __forceinline__ void grid_barrier() {
    __syncthreads();
    if (threadIdx.x == 0) {
        unsigned gen;
        asm volatile("ld.acquire.gpu.global.u32 %0, [%1];" : "=r"(gen) : "l"(&g_bar_gen));
        unsigned prev;
        asm volatile("atom.acq_rel.gpu.global.add.u32 %0, [%1], 1;" : "=r"(prev) : "l"(&g_bar_count));
        if (prev == NCTA - 1u) {
            asm volatile("st.relaxed.gpu.global.u32 [%0], %1;" :: "l"(&g_bar_count), "r"(0u));
            asm volatile("st.release.gpu.global.u32 [%0], %1;" :: "l"(&g_bar_gen), "r"(gen + 1u));
        } else {
            unsigned g2;
            do {
                asm volatile("ld.acquire.gpu.global.u32 %0, [%1];" : "=r"(g2) : "l"(&g_bar_gen));
            } while (g2 == gen);
        }
    }
    __syncthreads();
}

// ---- persistent scan: 16 rows x 32 batches per CTA (halved x traffic) ----
// CTA s: i = s>>1 (rows base=16i..), h = s&1 (batches 32h..32h+31).
// Compute thread ct: bq = ct&15 (batch pair), ks = ct>>4 (k slice of 32).
// Warp w: lanes 0-15 -> ks=2w, lanes 16-31 -> ks=2w+1 (shfl xor16 pre-reduce).
// W smem: wsm[k*16 + r + ks*4] = dup pair of W[base+r][k] (skew: disjoint banks).
// Reducer: o = ct>>1 (r=o>>4, bp=o&15), g = ct&1 sums partial halves; shfl xor1.
__global__ __launch_bounds__(TPB, 1) void scan_kernel(const float* __restrict__ layer_w,
                                                      const float* __restrict__ init_state) {
    extern __shared__ __align__(16) unsigned char dsm[];
    ull* wsm  = (ull*)dsm;                   // 16512 ull = 132096 B
    ull* part = (ull*)(dsm + 132096);        // 256 * 18 ull = 36864 B

    const int ct   = threadIdx.x;
    const int lane = ct & 31;
    const int w    = ct >> 5;                // warp 0..15
    const int bq   = ct & 15;
    const int ks   = ct >> 4;                // 0..31
    const int s    = blockIdx.x;
    const int i    = s >> 1, h = s & 1;
    const int base = i * 16;

    // W fill once (coalesced global reads, scattered smem dup-writes)
    for (int e = ct; e < 16384; e += TPB) {
        int r = e >> 10, k = e & 1023;
        float wv = layer_w[(size_t)(base + r)*1024 + k];
        wsm[(size_t)k*16 + r + (k >> 5)*4] = pack2(wv, wv);
    }

    // reducer/epilogue role
    const int o = ct >> 1, g = ct & 1;
    const int rr = o >> 4, rbp = o & 15;
    const int dg = base + rr;
    const int b0 = h*32 + 2*rbp;
    float xo0 = init_state[dg], xo1 = init_state[dg];
    int len0 = 0, len1 = 0;
    if (g == 0) { len0 = g_len[b0]; len1 = g_len[b0 + 1]; }

    const ull* wk = wsm + ks*4;   // skew-adjusted base; k*16 added per k
    __syncthreads();

    for (int t = 0; t < 512; ++t) {
        const float* xin  = g_x[t & 1];
        float*       xout = g_x[(t & 1) ^ 1];

        ull upre = 0ull;
        if (g == 0) upre = __ldcg((const ull*)&g_u[((size_t)t*1024 + dg)*64 + b0]);

        ull acc[16];
        #pragma unroll
        for (int q = 0; q < 16; ++q) acc[q] = 0ull;

        const float* xp = xin + (size_t)(ks * 32) * 64 + h*32 + 2*bq;

        // x double-buffer: chunks of 8 k, 1 ull (2 batches) per k
        ull xa[8], xb[8];
        #pragma unroll
        for (int j = 0; j < 8; ++j)
            xa[j] = __ldcg((const ull*)(xp + (size_t)j * 64));

        #pragma unroll
        for (int c = 0; c < 4; ++c) {
            ull* cur = (c & 1) ? xb : xa;
            ull* nxt = (c & 1) ? xa : xb;
            if (c < 3) {
                #pragma unroll
                for (int j = 0; j < 8; ++j)
                    nxt[j] = __ldcg((const ull*)(xp + (size_t)((c + 1)*8 + j) * 64));
            }
            #pragma unroll
            for (int j = 0; j < 8; ++j) {
                int k = ks*32 + c*8 + j;
                const ulonglong2* wp = (const ulonglong2*)(wk + (size_t)k * 16);
                ull xv = cur[j];
                ulonglong2 w0 = wp[0], w1 = wp[1], w2 = wp[2], w3 = wp[3];
                ulonglong2 w4 = wp[4], w5 = wp[5], w6 = wp[6], w7 = wp[7];
                acc[0]  = ffma2(xv, w0.x, acc[0]);  acc[1]  = ffma2(xv, w0.y, acc[1]);
                acc[2]  = ffma2(xv, w1.x, acc[2]);  acc[3]  = ffma2(xv, w1.y, acc[3]);
                acc[4]  = ffma2(xv, w2.x, acc[4]);  acc[5]  = ffma2(xv, w2.y, acc[5]);
                acc[6]  = ffma2(xv, w3.x, acc[6]);  acc[7]  = ffma2(xv, w3.y, acc[7]);
                acc[8]  = ffma2(xv, w4.x, acc[8]);  acc[9]  = ffma2(xv, w4.y, acc[9]);
                acc[10] = ffma2(xv, w5.x, acc[10]); acc[11] = ffma2(xv, w5.y, acc[11]);
                acc[12] = ffma2(xv, w6.x, acc[12]); acc[13] = ffma2(xv, w6.y, acc[13]);
                acc[14] = ffma2(xv, w7.x, acc[14]); acc[15] = ffma2(xv, w7.y, acc[15]);
            }
        }

        // in-warp pre-reduce: collapse the warp's two k-slices
        #pragma unroll
        for (int q = 0; q < 16; ++q)
            acc[q] = add2(acc[q], __shfl_xor_sync(0xffffffffu, acc[q], 16));

        if (lane < 16) {
            ull* prow = part + (size_t)(w*16 + lane) * 18;
            #pragma unroll
            for (int q = 0; q < 8; ++q)
                *(ulonglong2*)&prow[2*q] = make_ulonglong2(acc[2*q], acc[2*q+1]);
        }
        __syncthreads();

        // reduce 16 pre-reduced partials: each thread sums 8 (its g half)
        ull sacc = (g == 0) ? upre : 0ull;
        #pragma unroll
        for (int ww = 0; ww < 8; ++ww)
            sacc = add2(sacc, part[(size_t)((8*g + ww)*16 + rbp)*18 + rr]);
        sacc = add2(sacc, __shfl_xor_sync(0xffffffffu, sacc, 1));

        if (g == 0) {
            float2 a = unpk(sacc);
            float n0 = 0.5f * tanhf(a.x) + 0.5f * xo0;
            float n1 = 0.5f * tanhf(a.y) + 0.5f * xo1;
            if (t >= len0) n0 = 0.f;
            if (t >= len1) n1 = 0.f;
            xo0 = n0; xo1 = n1;

            __stcg((float2*)(xout + (size_t)dg*64 + b0), make_float2(n0, n1));
            *(float2*)&g_s[((size_t)t*1024 + dg)*64 + b0] = make_float2(n0, n1);
        }
        grid_barrier();
    }
}

// ---- transpose g_s[t][d][b] -> out[b][t][d] ----
__global__ __launch_bounds__(256) void trans_kernel(float* __restrict__ out) {
    __shared__ float ts[64][65];
    const int t  = blockIdx.y;
    const int d0 = blockIdx.x * 64;
    const int tid = threadIdx.x;
    #pragma unroll
    for (int j = 0; j < 16; ++j) {
        int idx = j*256 + tid;
        int dl = idx >> 6, b = idx & 63;
        ts[dl][b] = g_s[(((size_t)t << 10) + d0 + dl)*64 + b];
    }
    __syncthreads();
    #pragma unroll
    for (int j = 0; j < 16; ++j) {
        int idx = j*256 + tid;
        int b = idx >> 6, dl = idx & 63;
        out[((size_t)b*512 + t)*1024 + d0 + dl] = ts[dl][b];
    }
}

__global__ void tail_kernel(float* out) {
    int b = threadIdx.x;
    if (b < 64) out[33554432u + b] = (float)g_len[b];
}

extern "C" void kernel_launch(void* const* d_in, const int* in_sizes, int n_in,
                              void* d_out, int out_size) {
    const float* emb  = (const float*)d_in[0];
    const float* win  = (const float*)d_in[1];
    const float* lw   = (const float*)d_in[2];
    const float* bias = (const float*)d_in[3];
    const float* x0   = (const float*)d_in[4];
    float* out = (float*)d_out;

    static int smem_set = 0;
    if (!smem_set) {
        cudaFuncSetAttribute(scan_kernel, cudaFuncAttributeMaxDynamicSharedMemorySize, 168960);
        smem_set = 1;
    }

    init_kernel<<<256, 256>>>(x0);
    len_kernel<<<512, 256>>>(emb);
    proj_kernel<<<dim3(16, 256), 256>>>(emb, win, bias);
    scan_kernel<<<NCTA, TPB, 168960>>>(lw, x0);
    trans_kernel<<<dim3(16, 512), 256>>>(out);
    if (out_size >= 33554432 + 64) tail_kernel<<<1, 64>>>(out);
}

// round 13
// speedup vs baseline: 1.3183x; 1.3183x over previous
#include <cuda_runtime.h>
#include <math.h>

typedef unsigned long long ull;
#define NCTA 128
#define TPB  512
#define PSTRIDE 18

// ---- device scratch (static; allocations forbidden) ----
__device__ float g_u[512u*1024u*64u];   // u[t][d][b]
__device__ float g_s[512u*1024u*64u];   // states[t][d][b]
__device__ float g_x[2][1024*64];       // state ping-pong, layout [k][b]
__device__ int   g_len[64];
__device__ unsigned g_bar_count;
__device__ unsigned g_bar_gen;

// ---- packed f32x2 helpers ----
__device__ __forceinline__ ull pack2(float a, float b){ ull r; asm("mov.b64 %0,{%1,%2};":"=l"(r):"f"(a),"f"(b)); return r; }
__device__ __forceinline__ float2 unpk(ull v){ float2 r; asm("mov.b64 {%0,%1},%2;":"=f"(r.x),"=f"(r.y):"l"(v)); return r; }
__device__ __forceinline__ ull ffma2(ull a, ull b, ull c){ ull d; asm("fma.rn.f32x2 %0,%1,%2,%3;":"=l"(d):"l"(a),"l"(b),"l"(c)); return d; }
__device__ __forceinline__ ull add2(ull a, ull b){ ull d; asm("add.rn.f32x2 %0,%1,%2;":"=l"(d):"l"(a),"l"(b)); return d; }

// ---- init ----
__global__ void init_kernel(const float* __restrict__ x0) {
    int idx = blockIdx.x * 256 + threadIdx.x;
    g_x[0][idx] = x0[idx >> 6];
    if (idx < 64) g_len[idx] = 0;
}

// ---- lengths ----
__global__ void len_kernel(const float* __restrict__ emb) {
    int t = blockIdx.x;
    int b = threadIdx.x >> 2, p = threadIdx.x & 3;
    const float* row = emb + ((size_t)t*64 + b)*300;
    float s = 0.f;
    for (int i = p; i < 300; i += 4) s += row[i];
    s += __shfl_xor_sync(0xffffffffu, s, 1);
    s += __shfl_xor_sync(0xffffffffu, s, 2);
    if (p == 0 && s != 0.f) atomicAdd(&g_len[b], 1);
}

// ---- projection: 2 timesteps/block, float4-coalesced global loads ----
__global__ __launch_bounds__(256) void proj_kernel(const float* __restrict__ emb,
                                                   const float* __restrict__ win,
                                                   const float* __restrict__ bias) {
    __align__(16) __shared__ float Es[2][32][66];
    __align__(16) __shared__ ull   Wd[32][66];
    const int tid = threadIdx.x;
    const int tx = tid & 15;
    const int ty = tid >> 4;
    const int t0 = blockIdx.y * 2;
    const int d0 = blockIdx.x * 64;

    ull acc[2][4][2];
    #pragma unroll
    for (int h = 0; h < 2; ++h)
        #pragma unroll
        for (int i = 0; i < 4; ++i) { acc[h][i][0] = 0ull; acc[h][i][1] = 0ull; }

    for (int k0 = 0; k0 < 300; k0 += 32) {
        #pragma unroll
        for (int p = 0; p < 4; ++p) {
            int idx = tid + 256*p;
            int h = idx >> 9, rem = idx & 511;
            int b = rem >> 3, kq = rem & 7;
            int k = k0 + 4*kq;
            float4 v = make_float4(0.f, 0.f, 0.f, 0.f);
            if (k + 3 < 300) v = *(const float4*)&emb[((size_t)(t0+h)*64 + b)*300 + k];
            Es[h][4*kq+0][b] = v.x;
            Es[h][4*kq+1][b] = v.y;
            Es[h][4*kq+2][b] = v.z;
            Es[h][4*kq+3][b] = v.w;
        }
        #pragma unroll
        for (int p = 0; p < 2; ++p) {
            int idx = tid + 256*p;
            int dl = idx >> 3, kq = idx & 7;
            int k = k0 + 4*kq;
            float4 v = make_float4(0.f, 0.f, 0.f, 0.f);
            if (k + 3 < 300) v = *(const float4*)&win[((size_t)(d0+dl))*300 + k];
            Wd[4*kq+0][dl] = pack2(v.x, v.x);
            Wd[4*kq+1][dl] = pack2(v.y, v.y);
            Wd[4*kq+2][dl] = pack2(v.z, v.z);
            Wd[4*kq+3][dl] = pack2(v.w, v.w);
        }
        __syncthreads();
        #pragma unroll
        for (int kk = 0; kk < 32; ++kk) {
            ulonglong2 wA = *(const ulonglong2*)&Wd[kk][ty*4];
            ulonglong2 wB = *(const ulonglong2*)&Wd[kk][ty*4 + 2];
            #pragma unroll
            for (int h = 0; h < 2; ++h) {
                ull e01 = *(const ull*)&Es[h][kk][tx*4];
                ull e23 = *(const ull*)&Es[h][kk][tx*4 + 2];
                acc[h][0][0] = ffma2(e01, wA.x, acc[h][0][0]); acc[h][0][1] = ffma2(e23, wA.x, acc[h][0][1]);
                acc[h][1][0] = ffma2(e01, wA.y, acc[h][1][0]); acc[h][1][1] = ffma2(e23, wA.y, acc[h][1][1]);
                acc[h][2][0] = ffma2(e01, wB.x, acc[h][2][0]); acc[h][2][1] = ffma2(e23, wB.x, acc[h][2][1]);
                acc[h][3][0] = ffma2(e01, wB.y, acc[h][3][0]); acc[h][3][1] = ffma2(e23, wB.y, acc[h][3][1]);
            }
        }
        __syncthreads();
    }
    #pragma unroll
    for (int h = 0; h < 2; ++h)
        #pragma unroll
        for (int dd = 0; dd < 4; ++dd) {
            int d = d0 + ty*4 + dd;
            float bb = bias[d];
            float2 p0 = unpk(acc[h][dd][0]), p1 = unpk(acc[h][dd][1]);
            float4 o = make_float4(p0.x + bb, p0.y + bb, p1.x + bb, p1.y + bb);
            *(float4*)&g_u[((size_t)(t0+h)*1024 + d)*64 + tx*4] = o;
        }
}

// ---- grid barrier ----
__device__ __forceinline__ void grid_barrier() {
    __syncthreads();
    if (threadIdx.x == 0) {
        unsigned gen;
        asm volatile("ld.acquire.gpu.global.u32 %0, [%1];" : "=r"(gen) : "l"(&g_bar_gen));
        unsigned prev;
        asm volatile("atom.acq_rel.gpu.global.add.u32 %0, [%1], 1;" : "=r"(prev) : "l"(&g_bar_count));
        if (prev == NCTA - 1u) {
            asm volatile("st.relaxed.gpu.global.u32 [%0], %1;" :: "l"(&g_bar_count), "r"(0u));
            asm volatile("st.release.gpu.global.u32 [%0], %1;" :: "l"(&g_bar_gen), "r"(gen + 1u));
        } else {
            unsigned g2;
            do {
                asm volatile("ld.acquire.gpu.global.u32 %0, [%1];" : "=r"(g2) : "l"(&g_bar_gen));
            } while (g2 == gen);
        }
    }
    __syncthreads();
}

// ---- persistent scan: 16 rows x 32 batches, f32x2 over ROW-pairs ----
// CTA s: i = s>>1 (rows base=16i..16i+15), h = s&1 (batches 32h..32h+31).
// Compute thread: bq = ct&15 (batches 2bq,2bq+1 of the 32), ks = ct>>4 (32-k slice).
// W smem (natural pairs): wsm[k*8 + rp + (k>>5)*2] = (W[base+2rp][k], W[base+2rp+1][k]).
// acc[2*rp+bb] = f32x2 over (d=base+2rp, d=base+2rp+1) for batch 2bq+bb.
// Reducer (ct<256): dp = (ct>>5)&7, bp = ct&31 -> d-pair base+2dp, batch 32h+bp.
__global__ __launch_bounds__(TPB, 1) void scan_kernel(const float* __restrict__ layer_w,
                                                      const float* __restrict__ init_state) {
    extern __shared__ __align__(16) unsigned char dsm[];
    ull* wsm  = (ull*)dsm;                  // 8256 ull = 66048 B
    ull* part = (ull*)(dsm + 66048);        // 512 * PSTRIDE ull = 73728 B

    const int ct   = threadIdx.x;
    const int bq   = ct & 15;
    const int ks   = ct >> 4;               // 0..31
    const int s    = blockIdx.x;
    const int i    = s >> 1, h = s & 1;
    const int base = i * 16;

    // W natural-pair fill (once)
    for (int e = ct; e < 8192; e += TPB) {
        int rp = e >> 10, k = e & 1023;
        float w0 = layer_w[(size_t)(base + 2*rp    )*1024 + k];
        float w1 = layer_w[(size_t)(base + 2*rp + 1)*1024 + k];
        wsm[(size_t)k*8 + rp + (k >> 5)*2] = pack2(w0, w1);
    }

    // reducer role
    const int dp = (ct >> 5) & 7, bp = ct & 31;
    const int d0 = base + 2*dp;
    const int bg = h*32 + bp;
    float xo0 = init_state[d0], xo1 = init_state[d0 + 1];
    int lenb = 0;
    if (ct < 256) lenb = g_len[bg];

    const ull* wbase = wsm + (size_t)ks * 258;   // ks*32*8 + ks*2
    __syncthreads();

    for (int t = 0; t < 512; ++t) {
        const float* xin  = g_x[t & 1];
        float*       xout = g_x[(t & 1) ^ 1];

        ull upre = 0ull;
        if (ct < 256) {
            float u0 = __ldcg(&g_u[((size_t)t*1024 + d0    )*64 + bg]);
            float u1 = __ldcg(&g_u[((size_t)t*1024 + d0 + 1)*64 + bg]);
            upre = pack2(u0, u1);
        }

        ull acc[16];
        #pragma unroll
        for (int q = 0; q < 16; ++q) acc[q] = 0ull;

        const float* xp = xin + (size_t)(ks * 32) * 64 + h*32 + 2*bq;

        // double-buffered chunks of 8 k (x = float2 per k)
        float2 xa[8], xb[8];
        #pragma unroll
        for (int j = 0; j < 8; ++j)
            xa[j] = __ldcg((const float2*)(xp + (size_t)j * 64));

        #pragma unroll
        for (int c = 0; c < 4; ++c) {
            float2* cur = (c & 1) ? xb : xa;
            float2* nxt = (c & 1) ? xa : xb;
            if (c < 3) {
                #pragma unroll
                for (int j = 0; j < 8; ++j)
                    nxt[j] = __ldcg((const float2*)(xp + (size_t)((c + 1)*8 + j) * 64));
            }
            #pragma unroll
            for (int j = 0; j < 8; ++j) {
                const ulonglong2* wp = (const ulonglong2*)(wbase + (size_t)(c*8 + j) * 8);
                ull xd0 = pack2(cur[j].x, cur[j].x);
                ull xd1 = pack2(cur[j].y, cur[j].y);
                ulonglong2 wA = wp[0], wB = wp[1], wC = wp[2], wD = wp[3];
                acc[0]  = ffma2(xd0, wA.x, acc[0]);  acc[1]  = ffma2(xd1, wA.x, acc[1]);
                acc[2]  = ffma2(xd0, wA.y, acc[2]);  acc[3]  = ffma2(xd1, wA.y, acc[3]);
                acc[4]  = ffma2(xd0, wB.x, acc[4]);  acc[5]  = ffma2(xd1, wB.x, acc[5]);
                acc[6]  = ffma2(xd0, wB.y, acc[6]);  acc[7]  = ffma2(xd1, wB.y, acc[7]);
                acc[8]  = ffma2(xd0, wC.x, acc[8]);  acc[9]  = ffma2(xd1, wC.x, acc[9]);
                acc[10] = ffma2(xd0, wC.y, acc[10]); acc[11] = ffma2(xd1, wC.y, acc[11]);
                acc[12] = ffma2(xd0, wD.x, acc[12]); acc[13] = ffma2(xd1, wD.x, acc[13]);
                acc[14] = ffma2(xd0, wD.y, acc[14]); acc[15] = ffma2(xd1, wD.y, acc[15]);
            }
        }

        // partials: row ct, aligned vector stores
        ull* prow = part + (size_t)ct * PSTRIDE;
        #pragma unroll
        for (int q = 0; q < 8; ++q)
            *(ulonglong2*)&prow[2*q] = make_ulonglong2(acc[2*q], acc[2*q+1]);
        __syncthreads();

        if (ct < 256) {
            const int bq2 = bp >> 1, col = 2*dp + (bp & 1);
            ull s0 = upre, s1 = 0ull, s2 = 0ull, s3 = 0ull;
            #pragma unroll
            for (int kss = 0; kss < 32; kss += 4) {
                s0 = add2(s0, part[(size_t)((kss+0)*16 + bq2)*PSTRIDE + col]);
                s1 = add2(s1, part[(size_t)((kss+1)*16 + bq2)*PSTRIDE + col]);
                s2 = add2(s2, part[(size_t)((kss+2)*16 + bq2)*PSTRIDE + col]);
                s3 = add2(s3, part[(size_t)((kss+3)*16 + bq2)*PSTRIDE + col]);
            }
            ull ss = add2(add2(s0, s1), add2(s2, s3));

            float2 a = unpk(ss);
            float n0 = 0.5f * tanhf(a.x) + 0.5f * xo0;
            float n1 = 0.5f * tanhf(a.y) + 0.5f * xo1;
            if (t >= lenb) { n0 = 0.f; n1 = 0.f; }
            xo0 = n0; xo1 = n1;

            __stcg(xout + (size_t)(d0    )*64 + bg, n0);
            __stcg(xout + (size_t)(d0 + 1)*64 + bg, n1);
            g_s[((size_t)t*1024 + d0    )*64 + bg] = n0;
            g_s[((size_t)t*1024 + d0 + 1)*64 + bg] = n1;
        }
        grid_barrier();
    }
}

// ---- transpose g_s[t][d][b] -> out[b][t][d] ----
__global__ __launch_bounds__(256) void trans_kernel(float* __restrict__ out) {
    __shared__ float ts[64][65];
    const int t  = blockIdx.y;
    const int d0 = blockIdx.x * 64;
    const int tid = threadIdx.x;
    #pragma unroll
    for (int j = 0; j < 16; ++j) {
        int idx = j*256 + tid;
        int dl = idx >> 6, b = idx & 63;
        ts[dl][b] = g_s[(((size_t)t << 10) + d0 + dl)*64 + b];
    }
    __syncthreads();
    #pragma unroll
    for (int j = 0; j < 16; ++j) {
        int idx = j*256 + tid;
        int b = idx >> 6, dl = idx & 63;
        out[((size_t)b*512 + t)*1024 + d0 + dl] = ts[dl][b];
    }
}

__global__ void tail_kernel(float* out) {
    int b = threadIdx.x;
    if (b < 64) out[33554432u + b] = (float)g_len[b];
}

extern "C" void kernel_launch(void* const* d_in, const int* in_sizes, int n_in,
                              void* d_out, int out_size) {
    const float* emb  = (const float*)d_in[0];
    const float* win  = (const float*)d_in[1];
    const float* lw   = (const float*)d_in[2];
    const float* bias = (const float*)d_in[3];
    const float* x0   = (const float*)d_in[4];
    float* out = (float*)d_out;

    static int smem_set = 0;
    if (!smem_set) {
        cudaFuncSetAttribute(scan_kernel, cudaFuncAttributeMaxDynamicSharedMemorySize, 139776);
        smem_set = 1;
    }

    init_kernel<<<256, 256>>>(x0);
    len_kernel<<<512, 256>>>(emb);
    proj_kernel<<<dim3(16, 256), 256>>>(emb, win, bias);
    scan_kernel<<<NCTA, TPB, 139776>>>(lw, x0);
    trans_kernel<<<dim3(16, 512), 256>>>(out);
    if (out_size >= 33554432 + 64) tail_kernel<<<1, 64>>>(out);
}